// round 1
// baseline (speedup 1.0000x reference)
#include <cuda_runtime.h>
#include <cstdint>

// Problem constants (match reference)
#define U_DIM 2000
#define I_DIM 2000
#define K_DIM 32
#define B_DIM 16384
#define NEIGHBORHOOD 32.0f

// One warp per output element b. Lane k handles neighbor k (K==32==warpSize).
// qtus row load is fully coalesced (32 consecutive int32 = 128B line).
// weight / rating_matrix / b_item gathers are random -> L2-resident after warmup.
__global__ void __launch_bounds__(256) item_reg_kernel(
    const float* __restrict__ rating_matrix,  // [U, I]
    const int*   __restrict__ qtus,           // [U, I, K]
    const float* __restrict__ weight,         // [I, I]
    const float* __restrict__ b_user,         // [U]
    const float* __restrict__ b_item,         // [I]
    const int*   __restrict__ users,          // [B]
    const int*   __restrict__ items,          // [B]
    float*       __restrict__ out)            // [B]
{
    const int warp_id = (blockIdx.x * blockDim.x + threadIdx.x) >> 5;
    const int lane    = threadIdx.x & 31;
    if (warp_id >= B_DIM) return;

    const int u = users[warp_id];
    const int t = items[warp_id];

    // qtu index for this lane: qtus[u, t, lane]
    const long long qbase = ((long long)u * I_DIM + t) * K_DIM;
    const int j = __ldg(&qtus[qbase + lane]);

    const float bu = __ldg(&b_user[u]);

    // three independent gathers -> MLP=3 per lane
    const float w  = __ldg(&weight[(long long)j * I_DIM + t]);
    const float r  = __ldg(&rating_matrix[(long long)u * I_DIM + j]);
    const float bj = __ldg(&b_item[j]);

    float v = w * (r - bu - bj);

    // warp reduction
    #pragma unroll
    for (int off = 16; off > 0; off >>= 1)
        v += __shfl_down_sync(0xFFFFFFFFu, v, off);

    if (lane == 0) {
        const float bt = __ldg(&b_item[t]);
        out[warp_id] = bu + bt + v * (1.0f / NEIGHBORHOOD);
    }
}

extern "C" void kernel_launch(void* const* d_in, const int* in_sizes, int n_in,
                              void* d_out, int out_size)
{
    const float* rating_matrix = (const float*)d_in[0];
    const int*   qtus          = (const int*)  d_in[1];
    const float* weight        = (const float*)d_in[2];
    const float* b_user        = (const float*)d_in[3];
    const float* b_item        = (const float*)d_in[4];
    const int*   users         = (const int*)  d_in[5];
    const int*   items         = (const int*)  d_in[6];
    float* out = (float*)d_out;

    // one warp per b: 16384 warps, 8 warps (256 threads) per block -> 2048 blocks
    const int threads = 256;
    const int blocks  = (B_DIM * 32 + threads - 1) / threads;
    item_reg_kernel<<<blocks, threads>>>(rating_matrix, qtus, weight, b_user,
                                         b_item, users, items, out);
}

// round 2
// speedup vs baseline: 1.0029x; 1.0029x over previous
#include <cuda_runtime.h>
#include <cstdint>

// Problem constants (match reference)
#define U_DIM 2000
#define I_DIM 2000
#define K_DIM 32
#define B_DIM 16384
#define NEIGHBORHOOD 32.0f

#define THREADS 512
#define WARPS_PER_BLOCK (THREADS / 32)

// One warp per output element b. Lane k handles neighbor k (K==32==warpSize).
// qtus row load is fully coalesced (one 128B line per warp).
// b_item (8KB) is staged in shared memory -> random gather becomes LDS
// (conflict degree ~4) instead of ~25 L1tex wavefronts per warp.
__global__ void __launch_bounds__(THREADS) item_reg_kernel(
    const float* __restrict__ rating_matrix,  // [U, I]
    const int*   __restrict__ qtus,           // [U, I, K]
    const float* __restrict__ weight,         // [I, I]
    const float* __restrict__ b_user,         // [U]
    const float* __restrict__ b_item,         // [I]
    const int*   __restrict__ users,          // [B]
    const int*   __restrict__ items,          // [B]
    float*       __restrict__ out)            // [B]
{
    __shared__ float s_bitem[I_DIM];

    // Cooperative coalesced fill of b_item into smem (2000 floats = 8KB).
    #pragma unroll
    for (int i = threadIdx.x; i < I_DIM; i += THREADS)
        s_bitem[i] = b_item[i];

    const int warp_in_block = threadIdx.x >> 5;
    const int lane          = threadIdx.x & 31;
    const int b             = blockIdx.x * WARPS_PER_BLOCK + warp_in_block;

    // Load sample indices before the barrier to overlap with the smem fill.
    int u = 0, t = 0;
    if (b < B_DIM) {
        u = __ldg(&users[b]);
        t = __ldg(&items[b]);
    }

    __syncthreads();

    if (b >= B_DIM) return;

    // qtu index for this lane: qtus[u, t, lane]  (coalesced 128B line)
    const long long qbase = ((long long)u * I_DIM + t) * K_DIM;
    const int j = __ldg(&qtus[qbase + lane]);

    const float bu = __ldg(&b_user[u]);

    // two independent global gathers + one smem gather
    const float w  = __ldg(&weight[(long long)j * I_DIM + t]);
    const float r  = __ldg(&rating_matrix[(long long)u * I_DIM + j]);
    const float bj = s_bitem[j];

    float v = w * (r - bu - bj);

    // warp reduction
    #pragma unroll
    for (int off = 16; off > 0; off >>= 1)
        v += __shfl_down_sync(0xFFFFFFFFu, v, off);

    if (lane == 0) {
        const float bt = s_bitem[t];
        out[b] = bu + bt + v * (1.0f / NEIGHBORHOOD);
    }
}

extern "C" void kernel_launch(void* const* d_in, const int* in_sizes, int n_in,
                              void* d_out, int out_size)
{
    const float* rating_matrix = (const float*)d_in[0];
    const int*   qtus          = (const int*)  d_in[1];
    const float* weight        = (const float*)d_in[2];
    const float* b_user        = (const float*)d_in[3];
    const float* b_item        = (const float*)d_in[4];
    const int*   users         = (const int*)  d_in[5];
    const int*   items         = (const int*)  d_in[6];
    float* out = (float*)d_out;

    const int blocks = (B_DIM + WARPS_PER_BLOCK - 1) / WARPS_PER_BLOCK; // 1024
    item_reg_kernel<<<blocks, THREADS>>>(rating_matrix, qtus, weight, b_user,
                                         b_item, users, items, out);
}

// round 3
// speedup vs baseline: 1.0269x; 1.0239x over previous
#include <cuda_runtime.h>
#include <cstdint>

// Problem constants (match reference)
#define U_DIM 2000
#define I_DIM 2000
#define K_DIM 32
#define B_DIM 16384
#define NEIGHBORHOOD 32.0f

#define THREADS 256
#define WARPS_PER_BLOCK (THREADS / 32)
#define SPW 4   // samples per warp
#define SAMPLES_PER_BLOCK (WARPS_PER_BLOCK * SPW)   // 32

// One warp handles SPW=4 samples; lane k handles neighbor k of each.
// All loads for the 4 samples are issued in independent batches to raise
// per-warp MLP from 3 to 12 and amortize the dependent chain.
__global__ void __launch_bounds__(THREADS) item_reg_kernel(
    const float* __restrict__ rating_matrix,  // [U, I]
    const int*   __restrict__ qtus,           // [U, I, K]
    const float* __restrict__ weight,         // [I, I]
    const float* __restrict__ b_user,         // [U]
    const float* __restrict__ b_item,         // [I]
    const int*   __restrict__ users,          // [B]
    const int*   __restrict__ items,          // [B]
    float*       __restrict__ out)            // [B]
{
    __shared__ float s_bitem[I_DIM];

    // Cooperative coalesced fill of b_item into smem (2000 floats = 8KB).
    #pragma unroll
    for (int i = threadIdx.x; i < I_DIM; i += THREADS)
        s_bitem[i] = b_item[i];

    const int warp_in_block = threadIdx.x >> 5;
    const int lane          = threadIdx.x & 31;
    const int b0 = (blockIdx.x * WARPS_PER_BLOCK + warp_in_block) * SPW;

    // ---- batch 1: sample indices (uniform broadcast loads, independent) ----
    int u[SPW], t[SPW];
    #pragma unroll
    for (int s = 0; s < SPW; s++) {
        u[s] = __ldg(&users[b0 + s]);
        t[s] = __ldg(&items[b0 + s]);
    }

    __syncthreads();   // smem b_item ready

    // ---- batch 2: neighbor indices, 4 independent coalesced 128B loads ----
    int j[SPW];
    #pragma unroll
    for (int s = 0; s < SPW; s++) {
        const long long qbase = ((long long)u[s] * I_DIM + t[s]) * K_DIM;
        j[s] = __ldg(&qtus[qbase + lane]);
    }

    // ---- batch 3: user bias (uniform) ----
    float bu[SPW];
    #pragma unroll
    for (int s = 0; s < SPW; s++) bu[s] = __ldg(&b_user[u[s]]);

    // ---- batch 4: 8 independent scattered gathers ----
    float w[SPW], r[SPW];
    #pragma unroll
    for (int s = 0; s < SPW; s++) {
        w[s] = __ldg(&weight[(long long)j[s] * I_DIM + t[s]]);
        r[s] = __ldg(&rating_matrix[(long long)u[s] * I_DIM + j[s]]);
    }

    // ---- compute + interleaved reductions (shfl latencies overlap) ----
    float v[SPW];
    #pragma unroll
    for (int s = 0; s < SPW; s++)
        v[s] = w[s] * (r[s] - bu[s] - s_bitem[j[s]]);

    #pragma unroll
    for (int off = 16; off > 0; off >>= 1) {
        #pragma unroll
        for (int s = 0; s < SPW; s++)
            v[s] += __shfl_down_sync(0xFFFFFFFFu, v[s], off);
    }

    if (lane == 0) {
        #pragma unroll
        for (int s = 0; s < SPW; s++)
            out[b0 + s] = bu[s] + s_bitem[t[s]] + v[s] * (1.0f / NEIGHBORHOOD);
    }
}

extern "C" void kernel_launch(void* const* d_in, const int* in_sizes, int n_in,
                              void* d_out, int out_size)
{
    const float* rating_matrix = (const float*)d_in[0];
    const int*   qtus          = (const int*)  d_in[1];
    const float* weight        = (const float*)d_in[2];
    const float* b_user        = (const float*)d_in[3];
    const float* b_item        = (const float*)d_in[4];
    const int*   users         = (const int*)  d_in[5];
    const int*   items         = (const int*)  d_in[6];
    float* out = (float*)d_out;

    const int blocks = B_DIM / SAMPLES_PER_BLOCK;  // 512, all resident in one wave
    item_reg_kernel<<<blocks, THREADS>>>(rating_matrix, qtus, weight, b_user,
                                         b_item, users, items, out);
}